// round 5
// baseline (speedup 1.0000x reference)
#include <cuda_runtime.h>
#include <math.h>

#define Bb 2
#define Tt 512
#define Cc 256
#define Hh 8
#define Ee 32
#define NET 16
#define BT (Bb*Tt)      // 1024
#define C3 (3*Cc)       // 768

// ------- scratch (device globals: no allocation allowed) -------
__device__ float g_q[Bb*Hh*Tt*Ee];    // (b,h,t,e)
__device__ float g_k[Bb*Hh*Tt*Ee];
__device__ float g_v[Bb*Hh*Tt*Ee];
__device__ float g_ekt[2*Hh*NET*Ee];  // 2 k-split partials, [s][h][type][e]
__device__ float g_evt[2*Hh*NET*Ee];

// =====================================================================
// edge tables (k-split 2) + d_out zeroing, one launch
// blocks 0..31: edge partials; blocks 32..95: zero d_out
// =====================================================================
__global__ void __launch_bounds__(256) edge_zero(const float* __restrict__ eet,
                                                 const float* __restrict__ wek,
                                                 const float* __restrict__ wev,
                                                 float* __restrict__ out) {
    const int tid = threadIdx.x;
    const int bx = blockIdx.x;
    if (bx >= 32) {
        // zero d_out: 64 blocks x 256 threads x 4 float4 = 256K floats
        float4* o4 = (float4*)out;
        int base = (bx - 32) * 256 + tid;
        #pragma unroll
        for (int k = 0; k < 4; k++)
            o4[base + k * 16384] = make_float4(0.f, 0.f, 0.f, 0.f);
        return;
    }
    const int t = bx >> 1, s = bx & 1;     // type, k-half
    __shared__ float ee[128];
    if (tid < 128) ee[tid] = eet[t * Cc + s * 128 + tid];
    __syncthreads();
    const int c0 = tid;
    const int h = c0 >> 5, e = c0 & 31;
    float sk = 0.f, sv = 0.f;
    const float* wkp = wek + (size_t)(s * 128) * Cc + c0;
    const float* wvp = wev + (size_t)(s * 128) * Cc + c0;
    #pragma unroll 8
    for (int c = 0; c < 128; c++) {
        float a = ee[c];
        sk += a * wkp[c * Cc];
        sv += a * wvp[c * Cc];
    }
    g_ekt[s * (Hh*NET*Ee) + (h * NET + t) * Ee + e] = sk;
    g_evt[s * (Hh*NET*Ee) + (h * NET + t) * Ee + e] = sv;
}

// =====================================================================
// qkv GEMM: 32x128 tile, 256 threads, 2x8 micro, TK=32, double-buffered.
// A tile stored k-major (transposed). Fused reshape epilogue.
// =====================================================================
__global__ void __launch_bounds__(256) gemm_qkv(const float* __restrict__ A,
                                                const float* __restrict__ Bm) {
    __shared__ float As[2][32][34];    // [buf][kk][row], pad 34
    __shared__ float Bs[2][32][132];   // [buf][kk][col], pad 132 (16B-mult)
    const int tid = threadIdx.x;
    const int row0 = blockIdx.y * 32;
    const int col0 = blockIdx.x * 128;
    const int ar = tid >> 3, ac = (tid & 7) * 4;   // A: 32x32, 1 f4/thread
    const int br = tid >> 5, bc4 = tid & 31;       // B: 32x128, 4 f4/thread
    const int tr = tid >> 4, tc = tid & 15;

    float4 arg, brg[4];
    arg = *(const float4*)&A[(row0 + ar) * Cc + ac];
    #pragma unroll
    for (int p = 0; p < 4; p++)
        brg[p] = *(const float4*)&Bm[(br + p * 8) * C3 + col0 + bc4 * 4];
    {
        As[0][ac + 0][ar] = arg.x; As[0][ac + 1][ar] = arg.y;
        As[0][ac + 2][ar] = arg.z; As[0][ac + 3][ar] = arg.w;
        #pragma unroll
        for (int p = 0; p < 4; p++)
            *(float4*)&Bs[0][br + p * 8][bc4 * 4] = brg[p];
    }
    __syncthreads();

    float acc[2][8] = {};
    #pragma unroll 1
    for (int it = 0; it < 8; it++) {
        const int buf = it & 1;
        if (it < 7) {
            int k0 = (it + 1) * 32;
            arg = *(const float4*)&A[(row0 + ar) * Cc + k0 + ac];
            #pragma unroll
            for (int p = 0; p < 4; p++)
                brg[p] = *(const float4*)&Bm[(k0 + br + p * 8) * C3 + col0 + bc4 * 4];
        }
        #pragma unroll
        for (int kk = 0; kk < 32; kk++) {
            float2 a2 = *(const float2*)&As[buf][kk][tr * 2];
            float4 b0 = *(const float4*)&Bs[buf][kk][tc * 4];
            float4 b1 = *(const float4*)&Bs[buf][kk][64 + tc * 4];
            acc[0][0] += a2.x * b0.x; acc[0][1] += a2.x * b0.y;
            acc[0][2] += a2.x * b0.z; acc[0][3] += a2.x * b0.w;
            acc[0][4] += a2.x * b1.x; acc[0][5] += a2.x * b1.y;
            acc[0][6] += a2.x * b1.z; acc[0][7] += a2.x * b1.w;
            acc[1][0] += a2.y * b0.x; acc[1][1] += a2.y * b0.y;
            acc[1][2] += a2.y * b0.z; acc[1][3] += a2.y * b0.w;
            acc[1][4] += a2.y * b1.x; acc[1][5] += a2.y * b1.y;
            acc[1][6] += a2.y * b1.z; acc[1][7] += a2.y * b1.w;
        }
        if (it < 7) {
            const int nb = buf ^ 1;
            As[nb][ac + 0][ar] = arg.x; As[nb][ac + 1][ar] = arg.y;
            As[nb][ac + 2][ar] = arg.z; As[nb][ac + 3][ar] = arg.w;
            #pragma unroll
            for (int p = 0; p < 4; p++)
                *(float4*)&Bs[nb][br + p * 8][bc4 * 4] = brg[p];
            __syncthreads();
        }
    }
    // fused reshape epilogue: (bt, 3C) -> q/k/v (b,h,t,e), two col-halves
    #pragma unroll
    for (int half = 0; half < 2; half++) {
        int colbase = col0 + half * 64 + tc * 4;
        int which = colbase >> 8;
        float* dstArr = (which == 0) ? g_q : (which == 1) ? g_k : g_v;
        int h = (colbase & 255) >> 5;
        int e = colbase & 31;
        #pragma unroll
        for (int u = 0; u < 2; u++) {
            int row = row0 + tr * 2 + u;
            int b = row >> 9, t = row & 511;
            *(float4*)&dstArr[(((b * Hh + h) * Tt) + t) * Ee + e] =
                make_float4(acc[u][half*4+0], acc[u][half*4+1],
                            acc[u][half*4+2], acc[u][half*4+3]);
        }
    }
}

// ---------------- fused causal attention + projection ----------------
// grid (T/16, H, B), 256 threads (8 warps). Warp w -> rows i0+w, i0+w+8.
#define OFF_KS4   0                    // float4[64*8]        8192
#define OFF_VS    8192                 // float [64*33]       8448
#define OFF_QEK   16640                // float4[8*2*16*8]    32768 (reused as wp_s)
#define OFF_EVT   49408                // float [16*33]       2112
#define OFF_PE    51520                // float4[8*64]        8192  (reused as y_s)
#define OFF_ET    59712                // int   [64*17]       4352
#define OFF_EB    64064                // int   [16*65]       4160
#define OFF_BIAS  68224                // float [16]          64
#define SMEM_ATTN 68288

__global__ void __launch_bounds__(256) attn_kernel(const int* __restrict__ bm,
                                                   const float* __restrict__ abt,
                                                   const float* __restrict__ wproj,
                                                   float* __restrict__ out) {
    extern __shared__ char sm[];
    float4* ks4   = (float4*)(sm + OFF_KS4);
    float*  v_s   = (float*) (sm + OFF_VS);
    float4* qek4  = (float4*)(sm + OFF_QEK);
    float*  qekf  = (float*) (sm + OFF_QEK);
    float*  evt_s = (float*) (sm + OFF_EVT);
    float4* pe_s  = (float4*)(sm + OFF_PE);
    int*    et_s  = (int*)   (sm + OFF_ET);
    int*    eb_s  = (int*)   (sm + OFF_EB);
    float*  bias_s= (float*) (sm + OFF_BIAS);

    const int b = blockIdx.z, h = blockIdx.y;
    const int tid = threadIdx.x;
    const int w = tid >> 5, lane = tid & 31;
    const int itile = gridDim.x - 1 - blockIdx.x;   // heavy tiles first
    const int i0 = itile * 16;
    const int iA = i0 + w;
    const int iB = i0 + w + 8;

    const float* qb = g_q + (size_t)(b * Hh + h) * Tt * Ee;
    const float4* kb4 = (const float4*)(g_k + (size_t)(b * Hh + h) * Tt * Ee);
    const float4* vb4 = (const float4*)(g_v + (size_t)(b * Hh + h) * Tt * Ee);
    const int* bm_b = bm + (size_t)b * Tt * Tt;

    for (int x = tid; x < NET * Ee; x += 256)
        evt_s[(x >> 5) * 33 + (x & 31)] =
            g_evt[h * NET * Ee + x] + g_evt[Hh*NET*Ee + h * NET * Ee + x];
    if (tid < NET) bias_s[tid] = abt[tid * Hh + h];

    {   // per-warp modulated q tables for both rows
        float qA = qb[iA * Ee + lane];
        float qB = qb[iB * Ee + lane];
        int swzbase = lane >> 2;
        #pragma unroll
        for (int t = 0; t < NET; t++) {
            float ek = g_ekt[(h * NET + t) * Ee + lane]
                     + g_ekt[Hh*NET*Ee + (h * NET + t) * Ee + lane];
            int swz = ((swzbase ^ (t & 7)) << 2) | (lane & 3);
            qekf[((w * 2 + 0) * 16 + t) * 32 + swz] = qA * ek;
            qekf[((w * 2 + 1) * 16 + t) * 32 + swz] = qB * ek;
        }
    }
    __syncthreads();

    float mA = -INFINITY, lA = 0.f, mB = -INFINITY, lB = 0.f;
    float accA[4] = {}, accB[4] = {};
    const float inv_scale = 0.1767766952966369f;   // 1/sqrt(32)
    const int ntiles = ((i0 + 15) >> 6) + 1;

    for (int tile = 0; tile < ntiles; tile++) {
        const int j0 = tile * 64;
        #pragma unroll
        for (int x = tid; x < 512; x += 256) {
            int jj = x >> 3, c4 = x & 7;
            ks4[jj * 8 + (c4 ^ (jj & 7))] = kb4[(j0 + jj) * 8 + c4];
            float4 vv = vb4[(j0 + jj) * 8 + c4];
            float* vd = &v_s[jj * 33 + c4 * 4];
            vd[0] = vv.x; vd[1] = vv.y; vd[2] = vv.z; vd[3] = vv.w;
        }
        #pragma unroll
        for (int x = tid; x < 1024; x += 256) {
            int jj = x >> 4, iw = x & 15;
            et_s[jj * 17 + iw] = bm_b[(j0 + jj) * Tt + i0 + iw];
        }
        #pragma unroll
        for (int x = tid; x < 1024; x += 256) {
            int iw = x >> 6, jj = x & 63;
            eb_s[iw * 65 + jj] = bm_b[(i0 + iw) * Tt + j0 + jj];
        }
        __syncthreads();

        if (j0 <= iB) {
            const float4* krow = ks4 + lane * 8;
            const int kx = lane & 7;
            float sA0, sB0, sA1 = -INFINITY, sB1 = -INFINITY;
            int etA0, etB0, etA1 = 0, etB1 = 0;
            float pA1 = 0.f, pB1 = 0.f;

            {   // half 0: j = j0 + lane
                int jg = j0 + lane;
                etA0 = et_s[lane * 17 + w];
                etB0 = et_s[lane * 17 + w + 8];
                const float4* qrA = qek4 + ((w * 2 + 0) * 16 + etA0) * 8;
                const float4* qrB = qek4 + ((w * 2 + 1) * 16 + etB0) * 8;
                int qxA = etA0 & 7, qxB = etB0 & 7;
                float4 aA = {0,0,0,0}, aB = {0,0,0,0};
                #pragma unroll
                for (int c = 0; c < 8; c++) {
                    float4 k4 = krow[c ^ kx];
                    float4 qa = qrA[c ^ qxA];
                    float4 qc = qrB[c ^ qxB];
                    aA.x += qa.x * k4.x; aA.y += qa.y * k4.y;
                    aA.z += qa.z * k4.z; aA.w += qa.w * k4.w;
                    aB.x += qc.x * k4.x; aB.y += qc.y * k4.y;
                    aB.z += qc.z * k4.z; aB.w += qc.w * k4.w;
                }
                float dA = (aA.x + aA.y) + (aA.z + aA.w);
                float dB = (aB.x + aB.y) + (aB.z + aB.w);
                float bA = bias_s[eb_s[w * 65 + lane]];
                float bB = bias_s[eb_s[(w + 8) * 65 + lane]];
                sA0 = (jg <= iA) ? dA * inv_scale + bA : -INFINITY;
                sB0 = (jg <= iB) ? dB * inv_scale + bB : -INFINITY;
            }
            const bool h1 = (j0 + 32 <= iB);
            if (h1) {   // half 1: j = j0 + 32 + lane
                int jg = j0 + 32 + lane;
                etA1 = et_s[(32 + lane) * 17 + w];
                etB1 = et_s[(32 + lane) * 17 + w + 8];
                const float4* kr2 = ks4 + (32 + lane) * 8;
                const float4* qrA = qek4 + ((w * 2 + 0) * 16 + etA1) * 8;
                const float4* qrB = qek4 + ((w * 2 + 1) * 16 + etB1) * 8;
                int qxA = etA1 & 7, qxB = etB1 & 7;
                float4 aA = {0,0,0,0}, aB = {0,0,0,0};
                #pragma unroll
                for (int c = 0; c < 8; c++) {
                    float4 k4 = kr2[c ^ kx];
                    float4 qa = qrA[c ^ qxA];
                    float4 qc = qrB[c ^ qxB];
                    aA.x += qa.x * k4.x; aA.y += qa.y * k4.y;
                    aA.z += qa.z * k4.z; aA.w += qa.w * k4.w;
                    aB.x += qc.x * k4.x; aB.y += qc.y * k4.y;
                    aB.z += qc.z * k4.z; aB.w += qc.w * k4.w;
                }
                float dA = (aA.x + aA.y) + (aA.z + aA.w);
                float dB = (aB.x + aB.y) + (aB.z + aB.w);
                float bA = bias_s[eb_s[w * 65 + 32 + lane]];
                float bB = bias_s[eb_s[(w + 8) * 65 + 32 + lane]];
                sA1 = (jg <= iA) ? dA * inv_scale + bA : -INFINITY;
                sB1 = (jg <= iB) ? dB * inv_scale + bB : -INFINITY;
            }

            // online softmax, rows A and B
            float tA = fmaxf(sA0, sA1), tB = fmaxf(sB0, sB1);
            #pragma unroll
            for (int o = 16; o; o >>= 1) {
                tA = fmaxf(tA, __shfl_xor_sync(0xffffffffu, tA, o));
                tB = fmaxf(tB, __shfl_xor_sync(0xffffffffu, tB, o));
            }
            float mnA = fmaxf(mA, tA), mnB = fmaxf(mB, tB);
            float pA0 = __expf(sA0 - mnA), pB0 = __expf(sB0 - mnB);
            if (h1) { pA1 = __expf(sA1 - mnA); pB1 = __expf(sB1 - mnB); }
            float psA = pA0 + pA1, psB = pB0 + pB1;
            #pragma unroll
            for (int o = 16; o; o >>= 1) {
                psA += __shfl_xor_sync(0xffffffffu, psA, o);
                psB += __shfl_xor_sync(0xffffffffu, psB, o);
            }
            float cA = __expf(mA - mnA), cB = __expf(mB - mnB);
            lA = lA * cA + psA; lB = lB * cB + psB;
            mA = mnA; mB = mnB;
            #pragma unroll
            for (int u = 0; u < 4; u++) { accA[u] *= cA; accB[u] *= cB; }

            float4* pw = pe_s + w * 64;
            pw[lane] = make_float4(pA0, __int_as_float(etA0 * 132),
                                   pB0, __int_as_float(etB0 * 132));
            if (h1)
                pw[32 + lane] = make_float4(pA1, __int_as_float(etA1 * 132),
                                            pB1, __int_as_float(etB1 * 132));
            __syncwarp();

            // phase 2: lane = e
            int jlim = iB - j0 + 1; if (jlim > 64) jlim = 64;
            int jlim8 = (jlim + 7) & ~7;
            const float* vrow = v_s + lane;
            const char* evb = (const char*)evt_s + lane * 4;
            for (int j8 = 0; j8 < jlim8; j8 += 8) {
                #pragma unroll
                for (int u = 0; u < 8; u++) {
                    float4 pe = pw[j8 + u];
                    float vv = vrow[(j8 + u) * 33];
                    float evA = *(const float*)(evb + __float_as_int(pe.y));
                    float evB = *(const float*)(evb + __float_as_int(pe.w));
                    accA[u & 3] += (pe.x * vv) * evA;
                    accB[u & 3] += (pe.z * vv) * evB;
                }
            }
        }
        __syncthreads();
    }
    float oA = ((accA[0] + accA[1]) + (accA[2] + accA[3])) / lA;
    float oB = ((accB[0] + accB[1]) + (accB[2] + accB[3])) / lB;

    // ===== fused projection epilogue =====
    // reuse pe_s region as y_s[16][33], qek region as wp_s[32][256]
    float* y_s  = (float*)(sm + OFF_PE);
    float* wp_s = (float*)(sm + OFF_QEK);
    __syncthreads();                       // everyone done reading qek/pe
    y_s[w * 33 + lane] = oA;
    y_s[(w + 8) * 33 + lane] = oB;
    const float4* wpg = (const float4*)(wproj + (size_t)(h * 32) * Cc);
    #pragma unroll
    for (int p = 0; p < 8; p++) {
        int fidx = p * 256 + tid;          // f4 index: row = fidx>>6, c4 = fidx&63
        ((float4*)wp_s)[fidx] = wpg[fidx];
    }
    __syncthreads();

    const int r = tid & 15, g = tid >> 4;  // row 0..15, col-group 0..15
    float pacc[16] = {};
    const float* yrow = y_s + r * 33;
    #pragma unroll 4
    for (int e = 0; e < 32; e++) {
        float yv = yrow[e];
        const float4* wrow = (const float4*)(wp_s + e * 256 + g * 16);
        #pragma unroll
        for (int u = 0; u < 4; u++) {
            float4 w4 = wrow[u];
            pacc[u*4+0] += yv * w4.x; pacc[u*4+1] += yv * w4.y;
            pacc[u*4+2] += yv * w4.z; pacc[u*4+3] += yv * w4.w;
        }
    }
    float* orow = out + (size_t)(b * Tt + i0 + r) * Cc + g * 16;
    #pragma unroll
    for (int u = 0; u < 16; u++) atomicAdd(orow + u, pacc[u]);
}

// ---------------- launch ----------------
extern "C" void kernel_launch(void* const* d_in, const int* in_sizes, int n_in,
                              void* d_out, int out_size) {
    const float* x      = (const float*)d_in[0];
    const int*   bm     = (const int*)d_in[1];
    const float* w_attn = (const float*)d_in[2];
    const float* w_proj = (const float*)d_in[3];
    const float* w_ek   = (const float*)d_in[4];
    const float* w_ev   = (const float*)d_in[5];
    const float* eet    = (const float*)d_in[6];
    const float* abt    = (const float*)d_in[7];
    float* out = (float*)d_out;

    cudaFuncSetAttribute(attn_kernel, cudaFuncAttributeMaxDynamicSharedMemorySize, SMEM_ATTN);

    // edge-table partials + zero d_out
    edge_zero<<<96, 256>>>(eet, w_ek, w_ev, out);
    // qkv GEMM with fused reshape
    gemm_qkv<<<dim3(C3 / 128, BT / 32), 256>>>(x, w_attn);
    // fused attention + projection (atomicAdd into zeroed d_out)
    attn_kernel<<<dim3(Tt / 16, Hh, Bb), 256, SMEM_ATTN>>>(bm, abt, w_proj, out);
}

// round 6
// speedup vs baseline: 1.0571x; 1.0571x over previous
#include <cuda_runtime.h>
#include <math.h>

#define Bb 2
#define Tt 512
#define Cc 256
#define Hh 8
#define Ee 32
#define NET 16
#define BT (Bb*Tt)      // 1024
#define C3 (3*Cc)       // 768

// ------- scratch (device globals: no allocation allowed) -------
__device__ float g_q[Bb*Hh*Tt*Ee];    // (b,h,t,e)
__device__ float g_k[Bb*Hh*Tt*Ee];
__device__ float g_v[Bb*Hh*Tt*Ee];
__device__ float g_ekt[2*Hh*NET*Ee];  // 2 k-split partials, [s][h][type][e]
__device__ float g_evt[2*Hh*NET*Ee];
__device__ float g_y[BT*Cc];          // (b,t,c) pre-proj

// =====================================================================
// edge tables, k-split 2, high-MLP: 32 blocks (type, k-half), 256 thr.
// Explicit 16-wide register batching -> 32 loads in flight per thread.
// =====================================================================
__global__ void __launch_bounds__(256) edge_tables(const float* __restrict__ eet,
                                                   const float* __restrict__ wek,
                                                   const float* __restrict__ wev) {
    const int tid = threadIdx.x;
    const int t = blockIdx.x >> 1, s = blockIdx.x & 1;   // type, k-half
    __shared__ float ee[128];
    if (tid < 128) ee[tid] = eet[t * Cc + s * 128 + tid];
    __syncthreads();
    const int c0 = tid;
    const int h = c0 >> 5, e = c0 & 31;
    const float* wkp = wek + (size_t)(s * 128) * Cc + c0;
    const float* wvp = wev + (size_t)(s * 128) * Cc + c0;
    float sk0 = 0.f, sk1 = 0.f, sv0 = 0.f, sv1 = 0.f;
    #pragma unroll 1
    for (int cb = 0; cb < 128; cb += 16) {
        float wk[16], wv[16];
        #pragma unroll
        for (int u = 0; u < 16; u++) {
            wk[u] = wkp[(cb + u) * Cc];
            wv[u] = wvp[(cb + u) * Cc];
        }
        #pragma unroll
        for (int u = 0; u < 16; u += 2) {
            float a0 = ee[cb + u], a1 = ee[cb + u + 1];
            sk0 += a0 * wk[u];  sk1 += a1 * wk[u + 1];
            sv0 += a0 * wv[u];  sv1 += a1 * wv[u + 1];
        }
    }
    g_ekt[s * (Hh*NET*Ee) + (h * NET + t) * Ee + e] = sk0 + sk1;
    g_evt[s * (Hh*NET*Ee) + (h * NET + t) * Ee + e] = sv0 + sv1;
}

// =====================================================================
// qkv GEMM: 32x128 tile, 256 threads, 2x8 micro, TK=32, double-buffered.
// A tile stored k-major (transposed). Fused reshape epilogue.
// =====================================================================
__global__ void __launch_bounds__(256) gemm_qkv(const float* __restrict__ A,
                                                const float* __restrict__ Bm) {
    __shared__ float As[2][32][34];
    __shared__ float Bs[2][32][132];
    const int tid = threadIdx.x;
    const int row0 = blockIdx.y * 32;
    const int col0 = blockIdx.x * 128;
    const int ar = tid >> 3, ac = (tid & 7) * 4;
    const int br = tid >> 5, bc4 = tid & 31;
    const int tr = tid >> 4, tc = tid & 15;

    float4 arg, brg[4];
    arg = *(const float4*)&A[(row0 + ar) * Cc + ac];
    #pragma unroll
    for (int p = 0; p < 4; p++)
        brg[p] = *(const float4*)&Bm[(br + p * 8) * C3 + col0 + bc4 * 4];
    {
        As[0][ac + 0][ar] = arg.x; As[0][ac + 1][ar] = arg.y;
        As[0][ac + 2][ar] = arg.z; As[0][ac + 3][ar] = arg.w;
        #pragma unroll
        for (int p = 0; p < 4; p++)
            *(float4*)&Bs[0][br + p * 8][bc4 * 4] = brg[p];
    }
    __syncthreads();

    float acc[2][8] = {};
    #pragma unroll 1
    for (int it = 0; it < 8; it++) {
        const int buf = it & 1;
        if (it < 7) {
            int k0 = (it + 1) * 32;
            arg = *(const float4*)&A[(row0 + ar) * Cc + k0 + ac];
            #pragma unroll
            for (int p = 0; p < 4; p++)
                brg[p] = *(const float4*)&Bm[(k0 + br + p * 8) * C3 + col0 + bc4 * 4];
        }
        #pragma unroll
        for (int kk = 0; kk < 32; kk++) {
            float2 a2 = *(const float2*)&As[buf][kk][tr * 2];
            float4 b0 = *(const float4*)&Bs[buf][kk][tc * 4];
            float4 b1 = *(const float4*)&Bs[buf][kk][64 + tc * 4];
            acc[0][0] += a2.x * b0.x; acc[0][1] += a2.x * b0.y;
            acc[0][2] += a2.x * b0.z; acc[0][3] += a2.x * b0.w;
            acc[0][4] += a2.x * b1.x; acc[0][5] += a2.x * b1.y;
            acc[0][6] += a2.x * b1.z; acc[0][7] += a2.x * b1.w;
            acc[1][0] += a2.y * b0.x; acc[1][1] += a2.y * b0.y;
            acc[1][2] += a2.y * b0.z; acc[1][3] += a2.y * b0.w;
            acc[1][4] += a2.y * b1.x; acc[1][5] += a2.y * b1.y;
            acc[1][6] += a2.y * b1.z; acc[1][7] += a2.y * b1.w;
        }
        if (it < 7) {
            const int nb = buf ^ 1;
            As[nb][ac + 0][ar] = arg.x; As[nb][ac + 1][ar] = arg.y;
            As[nb][ac + 2][ar] = arg.z; As[nb][ac + 3][ar] = arg.w;
            #pragma unroll
            for (int p = 0; p < 4; p++)
                *(float4*)&Bs[nb][br + p * 8][bc4 * 4] = brg[p];
            __syncthreads();
        }
    }
    #pragma unroll
    for (int half = 0; half < 2; half++) {
        int colbase = col0 + half * 64 + tc * 4;
        int which = colbase >> 8;
        float* dstArr = (which == 0) ? g_q : (which == 1) ? g_k : g_v;
        int h = (colbase & 255) >> 5;
        int e = colbase & 31;
        #pragma unroll
        for (int u = 0; u < 2; u++) {
            int row = row0 + tr * 2 + u;
            int b = row >> 9, t = row & 511;
            *(float4*)&dstArr[(((b * Hh + h) * Tt) + t) * Ee + e] =
                make_float4(acc[u][half*4+0], acc[u][half*4+1],
                            acc[u][half*4+2], acc[u][half*4+3]);
        }
    }
}

// ==================== out = g_y @ w_proj, 32x64, double-buffered ====================
__global__ void __launch_bounds__(256) gemm_out(const float* __restrict__ A,
                                                const float* __restrict__ Bm,
                                                float* __restrict__ Cm) {
    __shared__ float As[2][32][40];
    __shared__ float Bs[2][32][72];
    const int tid = threadIdx.x;
    const int row0 = blockIdx.y * 32;
    const int col0 = blockIdx.x * 64;
    const int ar = tid >> 3, ac = (tid & 7) * 4;
    const int br = tid >> 4, bc = (tid & 15) * 4;
    const int tr = tid >> 4, tc = tid & 15;

    float4 arg, brg0, brg1;
    arg  = *(const float4*)&A[(row0 + ar) * Cc + ac];
    brg0 = *(const float4*)&Bm[br * Cc + col0 + bc];
    brg1 = *(const float4*)&Bm[(br + 16) * Cc + col0 + bc];
    *(float4*)&As[0][ar][ac] = arg;
    *(float4*)&Bs[0][br][bc] = brg0;
    *(float4*)&Bs[0][br + 16][bc] = brg1;
    __syncthreads();

    float acc[2][4] = {};
    #pragma unroll 1
    for (int it = 0; it < 8; it++) {
        const int buf = it & 1;
        if (it < 7) {
            int k0 = (it + 1) * 32;
            arg  = *(const float4*)&A[(row0 + ar) * Cc + k0 + ac];
            brg0 = *(const float4*)&Bm[(k0 + br) * Cc + col0 + bc];
            brg1 = *(const float4*)&Bm[(k0 + br + 16) * Cc + col0 + bc];
        }
        #pragma unroll
        for (int kk = 0; kk < 32; kk++) {
            float a0 = As[buf][tr * 2 + 0][kk];
            float a1 = As[buf][tr * 2 + 1][kk];
            float4 b4 = *(const float4*)&Bs[buf][kk][tc * 4];
            acc[0][0] += a0 * b4.x; acc[0][1] += a0 * b4.y;
            acc[0][2] += a0 * b4.z; acc[0][3] += a0 * b4.w;
            acc[1][0] += a1 * b4.x; acc[1][1] += a1 * b4.y;
            acc[1][2] += a1 * b4.z; acc[1][3] += a1 * b4.w;
        }
        if (it < 7) {
            const int nb = buf ^ 1;
            *(float4*)&As[nb][ar][ac] = arg;
            *(float4*)&Bs[nb][br][bc] = brg0;
            *(float4*)&Bs[nb][br + 16][bc] = brg1;
            __syncthreads();
        }
    }
    #pragma unroll
    for (int u = 0; u < 2; u++)
        *(float4*)&Cm[(row0 + tr * 2 + u) * Cc + col0 + tc * 4] =
            make_float4(acc[u][0], acc[u][1], acc[u][2], acc[u][3]);
}

// ---------------- fused causal attention: 2 query rows per warp ----------------
#define OFF_KS4   0                    // float4[64*8]        8192
#define OFF_VS    8192                 // float [64*33]       8448
#define OFF_QEK   16640                // float4[8*2*16*8]    32768
#define OFF_EVT   49408                // float [16*33]       2112
#define OFF_PE    51520                // float4[8*64]        8192
#define OFF_ET    59712                // int   [64*17]       4352
#define OFF_EB    64064                // int   [16*65]       4160
#define OFF_BIAS  68224                // float [16]          64
#define SMEM_ATTN 68288

__global__ void __launch_bounds__(256) attn_kernel(const int* __restrict__ bm,
                                                   const float* __restrict__ abt) {
    extern __shared__ char sm[];
    float4* ks4   = (float4*)(sm + OFF_KS4);
    float*  v_s   = (float*) (sm + OFF_VS);
    float4* qek4  = (float4*)(sm + OFF_QEK);
    float*  qekf  = (float*) (sm + OFF_QEK);
    float*  evt_s = (float*) (sm + OFF_EVT);
    float4* pe_s  = (float4*)(sm + OFF_PE);
    int*    et_s  = (int*)   (sm + OFF_ET);
    int*    eb_s  = (int*)   (sm + OFF_EB);
    float*  bias_s= (float*) (sm + OFF_BIAS);

    const int b = blockIdx.z, h = blockIdx.y;
    const int tid = threadIdx.x;
    const int w = tid >> 5, lane = tid & 31;
    const int itile = gridDim.x - 1 - blockIdx.x;   // heavy tiles first
    const int i0 = itile * 16;
    const int iA = i0 + w;
    const int iB = i0 + w + 8;

    const float* qb = g_q + (size_t)(b * Hh + h) * Tt * Ee;
    const float4* kb4 = (const float4*)(g_k + (size_t)(b * Hh + h) * Tt * Ee);
    const float4* vb4 = (const float4*)(g_v + (size_t)(b * Hh + h) * Tt * Ee);
    const int* bm_b = bm + (size_t)b * Tt * Tt;

    for (int x = tid; x < NET * Ee; x += 256)
        evt_s[(x >> 5) * 33 + (x & 31)] =
            g_evt[h * NET * Ee + x] + g_evt[Hh*NET*Ee + h * NET * Ee + x];
    if (tid < NET) bias_s[tid] = abt[tid * Hh + h];

    {   // per-warp modulated q tables for both rows
        float qA = qb[iA * Ee + lane];
        float qB = qb[iB * Ee + lane];
        int swzbase = lane >> 2;
        #pragma unroll
        for (int t = 0; t < NET; t++) {
            float ek = g_ekt[(h * NET + t) * Ee + lane]
                     + g_ekt[Hh*NET*Ee + (h * NET + t) * Ee + lane];
            int swz = ((swzbase ^ (t & 7)) << 2) | (lane & 3);
            qekf[((w * 2 + 0) * 16 + t) * 32 + swz] = qA * ek;
            qekf[((w * 2 + 1) * 16 + t) * 32 + swz] = qB * ek;
        }
    }
    __syncthreads();

    float mA = -INFINITY, lA = 0.f, mB = -INFINITY, lB = 0.f;
    float accA[4] = {}, accB[4] = {};
    const float inv_scale = 0.1767766952966369f;   // 1/sqrt(32)
    const int ntiles = ((i0 + 15) >> 6) + 1;

    for (int tile = 0; tile < ntiles; tile++) {
        const int j0 = tile * 64;
        #pragma unroll
        for (int x = tid; x < 512; x += 256) {
            int jj = x >> 3, c4 = x & 7;
            ks4[jj * 8 + (c4 ^ (jj & 7))] = kb4[(j0 + jj) * 8 + c4];
            float4 vv = vb4[(j0 + jj) * 8 + c4];
            float* vd = &v_s[jj * 33 + c4 * 4];
            vd[0] = vv.x; vd[1] = vv.y; vd[2] = vv.z; vd[3] = vv.w;
        }
        #pragma unroll
        for (int x = tid; x < 1024; x += 256) {
            int jj = x >> 4, iw = x & 15;
            et_s[jj * 17 + iw] = bm_b[(j0 + jj) * Tt + i0 + iw];
        }
        #pragma unroll
        for (int x = tid; x < 1024; x += 256) {
            int iw = x >> 6, jj = x & 63;
            eb_s[iw * 65 + jj] = bm_b[(i0 + iw) * Tt + j0 + jj];
        }
        __syncthreads();

        if (j0 <= iB) {
            const float4* krow = ks4 + lane * 8;
            const int kx = lane & 7;
            float sA0, sB0, sA1 = -INFINITY, sB1 = -INFINITY;
            int etA0, etB0, etA1 = 0, etB1 = 0;
            float pA1 = 0.f, pB1 = 0.f;

            {   // half 0: j = j0 + lane
                int jg = j0 + lane;
                etA0 = et_s[lane * 17 + w];
                etB0 = et_s[lane * 17 + w + 8];
                const float4* qrA = qek4 + ((w * 2 + 0) * 16 + etA0) * 8;
                const float4* qrB = qek4 + ((w * 2 + 1) * 16 + etB0) * 8;
                int qxA = etA0 & 7, qxB = etB0 & 7;
                float4 aA = {0,0,0,0}, aB = {0,0,0,0};
                #pragma unroll
                for (int c = 0; c < 8; c++) {
                    float4 k4 = krow[c ^ kx];
                    float4 qa = qrA[c ^ qxA];
                    float4 qc = qrB[c ^ qxB];
                    aA.x += qa.x * k4.x; aA.y += qa.y * k4.y;
                    aA.z += qa.z * k4.z; aA.w += qa.w * k4.w;
                    aB.x += qc.x * k4.x; aB.y += qc.y * k4.y;
                    aB.z += qc.z * k4.z; aB.w += qc.w * k4.w;
                }
                float dA = (aA.x + aA.y) + (aA.z + aA.w);
                float dB = (aB.x + aB.y) + (aB.z + aB.w);
                float bA = bias_s[eb_s[w * 65 + lane]];
                float bB = bias_s[eb_s[(w + 8) * 65 + lane]];
                sA0 = (jg <= iA) ? dA * inv_scale + bA : -INFINITY;
                sB0 = (jg <= iB) ? dB * inv_scale + bB : -INFINITY;
            }
            const bool h1 = (j0 + 32 <= iB);
            if (h1) {   // half 1: j = j0 + 32 + lane
                int jg = j0 + 32 + lane;
                etA1 = et_s[(32 + lane) * 17 + w];
                etB1 = et_s[(32 + lane) * 17 + w + 8];
                const float4* kr2 = ks4 + (32 + lane) * 8;
                const float4* qrA = qek4 + ((w * 2 + 0) * 16 + etA1) * 8;
                const float4* qrB = qek4 + ((w * 2 + 1) * 16 + etB1) * 8;
                int qxA = etA1 & 7, qxB = etB1 & 7;
                float4 aA = {0,0,0,0}, aB = {0,0,0,0};
                #pragma unroll
                for (int c = 0; c < 8; c++) {
                    float4 k4 = kr2[c ^ kx];
                    float4 qa = qrA[c ^ qxA];
                    float4 qc = qrB[c ^ qxB];
                    aA.x += qa.x * k4.x; aA.y += qa.y * k4.y;
                    aA.z += qa.z * k4.z; aA.w += qa.w * k4.w;
                    aB.x += qc.x * k4.x; aB.y += qc.y * k4.y;
                    aB.z += qc.z * k4.z; aB.w += qc.w * k4.w;
                }
                float dA = (aA.x + aA.y) + (aA.z + aA.w);
                float dB = (aB.x + aB.y) + (aB.z + aB.w);
                float bA = bias_s[eb_s[w * 65 + 32 + lane]];
                float bB = bias_s[eb_s[(w + 8) * 65 + 32 + lane]];
                sA1 = (jg <= iA) ? dA * inv_scale + bA : -INFINITY;
                sB1 = (jg <= iB) ? dB * inv_scale + bB : -INFINITY;
            }

            // online softmax, rows A and B
            float tA = fmaxf(sA0, sA1), tB = fmaxf(sB0, sB1);
            #pragma unroll
            for (int o = 16; o; o >>= 1) {
                tA = fmaxf(tA, __shfl_xor_sync(0xffffffffu, tA, o));
                tB = fmaxf(tB, __shfl_xor_sync(0xffffffffu, tB, o));
            }
            float mnA = fmaxf(mA, tA), mnB = fmaxf(mB, tB);
            float pA0 = __expf(sA0 - mnA), pB0 = __expf(sB0 - mnB);
            if (h1) { pA1 = __expf(sA1 - mnA); pB1 = __expf(sB1 - mnB); }
            float psA = pA0 + pA1, psB = pB0 + pB1;
            #pragma unroll
            for (int o = 16; o; o >>= 1) {
                psA += __shfl_xor_sync(0xffffffffu, psA, o);
                psB += __shfl_xor_sync(0xffffffffu, psB, o);
            }
            float cA = __expf(mA - mnA), cB = __expf(mB - mnB);
            lA = lA * cA + psA; lB = lB * cB + psB;
            mA = mnA; mB = mnB;
            #pragma unroll
            for (int u = 0; u < 4; u++) { accA[u] *= cA; accB[u] *= cB; }

            float4* pw = pe_s + w * 64;
            pw[lane] = make_float4(pA0, __int_as_float(etA0 * 132),
                                   pB0, __int_as_float(etB0 * 132));
            if (h1)
                pw[32 + lane] = make_float4(pA1, __int_as_float(etA1 * 132),
                                            pB1, __int_as_float(etB1 * 132));
            __syncwarp();

            // phase 2: lane = e
            int jlim = iB - j0 + 1; if (jlim > 64) jlim = 64;
            int jlim8 = (jlim + 7) & ~7;
            const float* vrow = v_s + lane;
            const char* evb = (const char*)evt_s + lane * 4;
            for (int j8 = 0; j8 < jlim8; j8 += 8) {
                #pragma unroll
                for (int u = 0; u < 8; u++) {
                    float4 pe = pw[j8 + u];
                    float vv = vrow[(j8 + u) * 33];
                    float evA = *(const float*)(evb + __float_as_int(pe.y));
                    float evB = *(const float*)(evb + __float_as_int(pe.w));
                    accA[u & 3] += (pe.x * vv) * evA;
                    accB[u & 3] += (pe.z * vv) * evB;
                }
            }
        }
        __syncthreads();
    }
    float oA = ((accA[0] + accA[1]) + (accA[2] + accA[3])) / lA;
    float oB = ((accB[0] + accB[1]) + (accB[2] + accB[3])) / lB;
    g_y[(size_t)(b * Tt + iA) * Cc + h * Ee + lane] = oA;
    g_y[(size_t)(b * Tt + iB) * Cc + h * Ee + lane] = oB;
}

// ---------------- launch ----------------
extern "C" void kernel_launch(void* const* d_in, const int* in_sizes, int n_in,
                              void* d_out, int out_size) {
    const float* x      = (const float*)d_in[0];
    const int*   bm     = (const int*)d_in[1];
    const float* w_attn = (const float*)d_in[2];
    const float* w_proj = (const float*)d_in[3];
    const float* w_ek   = (const float*)d_in[4];
    const float* w_ev   = (const float*)d_in[5];
    const float* eet    = (const float*)d_in[6];
    const float* abt    = (const float*)d_in[7];
    float* out = (float*)d_out;

    float* gy; cudaGetSymbolAddress((void**)&gy, g_y);

    cudaFuncSetAttribute(attn_kernel, cudaFuncAttributeMaxDynamicSharedMemorySize, SMEM_ATTN);

    edge_tables<<<32, 256>>>(eet, w_ek, w_ev);
    gemm_qkv<<<dim3(C3 / 128, BT / 32), 256>>>(x, w_attn);
    attn_kernel<<<dim3(Tt / 16, Hh, Bb), 256, SMEM_ATTN>>>(bm, abt);
    gemm_out<<<dim3(Cc / 64, BT / 32), 256>>>(gy, w_proj, out);
}

// round 7
// speedup vs baseline: 1.1267x; 1.0658x over previous
#include <cuda_runtime.h>
#include <math.h>

#define Bb 2
#define Tt 512
#define Cc 256
#define Hh 8
#define Ee 32
#define NET 16
#define BT (Bb*Tt)      // 1024
#define C3 (3*Cc)       // 768

// ------- scratch (device globals: no allocation allowed) -------
__device__ float g_q[Bb*Hh*Tt*Ee];    // (b,h,t,e)
__device__ float g_k[Bb*Hh*Tt*Ee];
__device__ float g_v[Bb*Hh*Tt*Ee];
__device__ float g_ekt[4*Hh*NET*Ee];  // 4 k-split partials, [s][h][type][e]
__device__ float g_evt[4*Hh*NET*Ee];
__device__ float g_y[BT*Cc];          // (b,t,c) pre-proj

// =====================================================================
// qkv GEMM: 32x64 tile, TK=32, double-buffered (proven structure).
// grid (14, 32): bx 0..11 compute, bx 12..13 -> 64 edge-table blocks
// (16 types x 4-way k-split, high-MLP batched loads, ~1.5us each).
// =====================================================================
__global__ void __launch_bounds__(256) gemm_qkv(const float* __restrict__ A,
                                                const float* __restrict__ Bm,
                                                const float* __restrict__ eet,
                                                const float* __restrict__ wek,
                                                const float* __restrict__ wev) {
    const int tid = threadIdx.x;
    const int bx = blockIdx.x;

    if (bx >= 12) {
        // ---- edge-table partial block ----
        const int id = (bx - 12) * 32 + blockIdx.y;   // 0..63
        const int t = id >> 2, s4 = id & 3;           // type, k-quarter
        __shared__ float ee[64];
        if (tid < 64) ee[tid] = eet[t * Cc + s4 * 64 + tid];
        __syncthreads();
        const int c0 = tid;
        const int h = c0 >> 5, e = c0 & 31;
        const float* wkp = wek + (size_t)(s4 * 64) * Cc + c0;
        const float* wvp = wev + (size_t)(s4 * 64) * Cc + c0;
        float sk0 = 0.f, sk1 = 0.f, sv0 = 0.f, sv1 = 0.f;
        #pragma unroll 1
        for (int cb = 0; cb < 64; cb += 16) {
            float wk[16], wv[16];
            #pragma unroll
            for (int u = 0; u < 16; u++) {
                wk[u] = wkp[(cb + u) * Cc];
                wv[u] = wvp[(cb + u) * Cc];
            }
            #pragma unroll
            for (int u = 0; u < 16; u += 2) {
                float a0 = ee[cb + u], a1 = ee[cb + u + 1];
                sk0 += a0 * wk[u];  sk1 += a1 * wk[u + 1];
                sv0 += a0 * wv[u];  sv1 += a1 * wv[u + 1];
            }
        }
        g_ekt[s4 * (Hh*NET*Ee) + (h * NET + t) * Ee + e] = sk0 + sk1;
        g_evt[s4 * (Hh*NET*Ee) + (h * NET + t) * Ee + e] = sv0 + sv1;
        return;
    }

    // ---- 32x64 GEMM compute block ----
    __shared__ float As[2][32][40];
    __shared__ float Bs[2][32][72];
    const int row0 = blockIdx.y * 32;
    const int col0 = bx * 64;
    const int ar = tid >> 3, ac = (tid & 7) * 4;
    const int br = tid >> 4, bc = (tid & 15) * 4;
    const int tr = tid >> 4, tc = tid & 15;

    float4 arg, brg0, brg1;
    arg  = *(const float4*)&A[(row0 + ar) * Cc + ac];
    brg0 = *(const float4*)&Bm[br * C3 + col0 + bc];
    brg1 = *(const float4*)&Bm[(br + 16) * C3 + col0 + bc];
    *(float4*)&As[0][ar][ac] = arg;
    *(float4*)&Bs[0][br][bc] = brg0;
    *(float4*)&Bs[0][br + 16][bc] = brg1;
    __syncthreads();

    float acc[2][4] = {};
    #pragma unroll 1
    for (int it = 0; it < 8; it++) {
        const int buf = it & 1;
        if (it < 7) {
            int k0 = (it + 1) * 32;
            arg  = *(const float4*)&A[(row0 + ar) * Cc + k0 + ac];
            brg0 = *(const float4*)&Bm[(k0 + br) * C3 + col0 + bc];
            brg1 = *(const float4*)&Bm[(k0 + br + 16) * C3 + col0 + bc];
        }
        #pragma unroll
        for (int kk = 0; kk < 32; kk++) {
            float a0 = As[buf][tr * 2 + 0][kk];
            float a1 = As[buf][tr * 2 + 1][kk];
            float4 b4 = *(const float4*)&Bs[buf][kk][tc * 4];
            acc[0][0] += a0 * b4.x; acc[0][1] += a0 * b4.y;
            acc[0][2] += a0 * b4.z; acc[0][3] += a0 * b4.w;
            acc[1][0] += a1 * b4.x; acc[1][1] += a1 * b4.y;
            acc[1][2] += a1 * b4.z; acc[1][3] += a1 * b4.w;
        }
        if (it < 7) {
            const int nb = buf ^ 1;
            *(float4*)&As[nb][ar][ac] = arg;
            *(float4*)&Bs[nb][br][bc] = brg0;
            *(float4*)&Bs[nb][br + 16][bc] = brg1;
            __syncthreads();
        }
    }
    // fused reshape epilogue: (bt, 3C) -> q/k/v (b,h,t,e)
    int colbase = col0 + tc * 4;
    int which = colbase >> 8;
    float* dstArr = (which == 0) ? g_q : (which == 1) ? g_k : g_v;
    int h = (colbase & 255) >> 5;
    int e = colbase & 31;
    #pragma unroll
    for (int u = 0; u < 2; u++) {
        int row = row0 + tr * 2 + u;
        int b = row >> 9, t = row & 511;
        *(float4*)&dstArr[(((b * Hh + h) * Tt) + t) * Ee + e] =
            make_float4(acc[u][0], acc[u][1], acc[u][2], acc[u][3]);
    }
}

// ==================== out = g_y @ w_proj, 32x32 tiles, 256 blocks ====================
__global__ void __launch_bounds__(256) gemm_out(const float* __restrict__ A,
                                                const float* __restrict__ Bm,
                                                float* __restrict__ Cm) {
    __shared__ float As[2][32][33];    // [buf][row][k], pad 33 (conflict-free col reads)
    __shared__ float Bs[2][32][36];    // [buf][k][col], pad 36 (16B aligned rows)
    const int tid = threadIdx.x;
    const int row0 = blockIdx.y * 32;
    const int col0 = blockIdx.x * 32;
    const int ar = tid >> 3, ac = (tid & 7) * 4;   // both tiles: 32x32, 1 f4/thread
    const int r = tid >> 3, cg = (tid & 7) * 4;    // micro: 1 row x 4 cols

    float4 arg, brg;
    arg = *(const float4*)&A[(row0 + ar) * Cc + ac];
    brg = *(const float4*)&Bm[ar * Cc + col0 + ac];
    As[0][ar][ac+0] = arg.x; As[0][ar][ac+1] = arg.y;
    As[0][ar][ac+2] = arg.z; As[0][ar][ac+3] = arg.w;
    *(float4*)&Bs[0][ar][ac] = brg;
    __syncthreads();

    float acc[4] = {};
    #pragma unroll 1
    for (int it = 0; it < 8; it++) {
        const int buf = it & 1;
        if (it < 7) {
            int k0 = (it + 1) * 32;
            arg = *(const float4*)&A[(row0 + ar) * Cc + k0 + ac];
            brg = *(const float4*)&Bm[(k0 + ar) * Cc + col0 + ac];
        }
        #pragma unroll
        for (int kk = 0; kk < 32; kk++) {
            float a = As[buf][r][kk];
            float4 b4 = *(const float4*)&Bs[buf][kk][cg];
            acc[0] += a * b4.x; acc[1] += a * b4.y;
            acc[2] += a * b4.z; acc[3] += a * b4.w;
        }
        if (it < 7) {
            const int nb = buf ^ 1;
            As[nb][ar][ac+0] = arg.x; As[nb][ar][ac+1] = arg.y;
            As[nb][ar][ac+2] = arg.z; As[nb][ar][ac+3] = arg.w;
            *(float4*)&Bs[nb][ar][ac] = brg;
            __syncthreads();
        }
    }
    *(float4*)&Cm[(row0 + r) * Cc + col0 + cg] =
        make_float4(acc[0], acc[1], acc[2], acc[3]);
}

// ---------------- fused causal attention: 2 query rows per warp ----------------
#define OFF_KS4   0                    // float4[64*8]        8192
#define OFF_VS    8192                 // float [64*33]       8448
#define OFF_QEK   16640                // float4[8*2*16*8]    32768
#define OFF_EVT   49408                // float [16*33]       2112
#define OFF_PE    51520                // float4[8*64]        8192
#define OFF_ET    59712                // int   [64*17]       4352
#define OFF_EB    64064                // int   [16*65]       4160
#define OFF_BIAS  68224                // float [16]          64
#define SMEM_ATTN 68288

__global__ void __launch_bounds__(256) attn_kernel(const int* __restrict__ bm,
                                                   const float* __restrict__ abt) {
    extern __shared__ char sm[];
    float4* ks4   = (float4*)(sm + OFF_KS4);
    float*  v_s   = (float*) (sm + OFF_VS);
    float4* qek4  = (float4*)(sm + OFF_QEK);
    float*  qekf  = (float*) (sm + OFF_QEK);
    float*  evt_s = (float*) (sm + OFF_EVT);
    float4* pe_s  = (float4*)(sm + OFF_PE);
    int*    et_s  = (int*)   (sm + OFF_ET);
    int*    eb_s  = (int*)   (sm + OFF_EB);
    float*  bias_s= (float*) (sm + OFF_BIAS);

    const int b = blockIdx.z, h = blockIdx.y;
    const int tid = threadIdx.x;
    const int w = tid >> 5, lane = tid & 31;
    const int itile = gridDim.x - 1 - blockIdx.x;   // heavy tiles first
    const int i0 = itile * 16;
    const int iA = i0 + w;
    const int iB = i0 + w + 8;

    const float* qb = g_q + (size_t)(b * Hh + h) * Tt * Ee;
    const float4* kb4 = (const float4*)(g_k + (size_t)(b * Hh + h) * Tt * Ee);
    const float4* vb4 = (const float4*)(g_v + (size_t)(b * Hh + h) * Tt * Ee);
    const int* bm_b = bm + (size_t)b * Tt * Tt;

    for (int x = tid; x < NET * Ee; x += 256) {
        float ev = g_evt[h * NET * Ee + x]
                 + g_evt[1*Hh*NET*Ee + h * NET * Ee + x]
                 + g_evt[2*Hh*NET*Ee + h * NET * Ee + x]
                 + g_evt[3*Hh*NET*Ee + h * NET * Ee + x];
        evt_s[(x >> 5) * 33 + (x & 31)] = ev;
    }
    if (tid < NET) bias_s[tid] = abt[tid * Hh + h];

    {   // per-warp modulated q tables for both rows
        float qA = qb[iA * Ee + lane];
        float qB = qb[iB * Ee + lane];
        int swzbase = lane >> 2;
        #pragma unroll
        for (int t = 0; t < NET; t++) {
            int idx = (h * NET + t) * Ee + lane;
            float ek = g_ekt[idx] + g_ekt[1*Hh*NET*Ee + idx]
                     + g_ekt[2*Hh*NET*Ee + idx] + g_ekt[3*Hh*NET*Ee + idx];
            int swz = ((swzbase ^ (t & 7)) << 2) | (lane & 3);
            qekf[((w * 2 + 0) * 16 + t) * 32 + swz] = qA * ek;
            qekf[((w * 2 + 1) * 16 + t) * 32 + swz] = qB * ek;
        }
    }
    __syncthreads();

    float mA = -INFINITY, lA = 0.f, mB = -INFINITY, lB = 0.f;
    float accA[4] = {}, accB[4] = {};
    const float inv_scale = 0.1767766952966369f;   // 1/sqrt(32)
    const int ntiles = ((i0 + 15) >> 6) + 1;

    for (int tile = 0; tile < ntiles; tile++) {
        const int j0 = tile * 64;
        #pragma unroll
        for (int x = tid; x < 512; x += 256) {
            int jj = x >> 3, c4 = x & 7;
            ks4[jj * 8 + (c4 ^ (jj & 7))] = kb4[(j0 + jj) * 8 + c4];
            float4 vv = vb4[(j0 + jj) * 8 + c4];
            float* vd = &v_s[jj * 33 + c4 * 4];
            vd[0] = vv.x; vd[1] = vv.y; vd[2] = vv.z; vd[3] = vv.w;
        }
        #pragma unroll
        for (int x = tid; x < 1024; x += 256) {
            int jj = x >> 4, iw = x & 15;
            et_s[jj * 17 + iw] = bm_b[(j0 + jj) * Tt + i0 + iw];
        }
        #pragma unroll
        for (int x = tid; x < 1024; x += 256) {
            int iw = x >> 6, jj = x & 63;
            eb_s[iw * 65 + jj] = bm_b[(i0 + iw) * Tt + j0 + jj];
        }
        __syncthreads();

        if (j0 <= iB) {
            const float4* krow = ks4 + lane * 8;
            const int kx = lane & 7;
            float sA0, sB0, sA1 = -INFINITY, sB1 = -INFINITY;
            int etA0, etB0, etA1 = 0, etB1 = 0;
            float pA1 = 0.f, pB1 = 0.f;

            {   // half 0: j = j0 + lane
                int jg = j0 + lane;
                etA0 = et_s[lane * 17 + w];
                etB0 = et_s[lane * 17 + w + 8];
                const float4* qrA = qek4 + ((w * 2 + 0) * 16 + etA0) * 8;
                const float4* qrB = qek4 + ((w * 2 + 1) * 16 + etB0) * 8;
                int qxA = etA0 & 7, qxB = etB0 & 7;
                float4 aA = {0,0,0,0}, aB = {0,0,0,0};
                #pragma unroll
                for (int c = 0; c < 8; c++) {
                    float4 k4 = krow[c ^ kx];
                    float4 qa = qrA[c ^ qxA];
                    float4 qc = qrB[c ^ qxB];
                    aA.x += qa.x * k4.x; aA.y += qa.y * k4.y;
                    aA.z += qa.z * k4.z; aA.w += qa.w * k4.w;
                    aB.x += qc.x * k4.x; aB.y += qc.y * k4.y;
                    aB.z += qc.z * k4.z; aB.w += qc.w * k4.w;
                }
                float dA = (aA.x + aA.y) + (aA.z + aA.w);
                float dB = (aB.x + aB.y) + (aB.z + aB.w);
                float bA = bias_s[eb_s[w * 65 + lane]];
                float bB = bias_s[eb_s[(w + 8) * 65 + lane]];
                sA0 = (jg <= iA) ? dA * inv_scale + bA : -INFINITY;
                sB0 = (jg <= iB) ? dB * inv_scale + bB : -INFINITY;
            }
            const bool h1 = (j0 + 32 <= iB);
            if (h1) {   // half 1: j = j0 + 32 + lane
                int jg = j0 + 32 + lane;
                etA1 = et_s[(32 + lane) * 17 + w];
                etB1 = et_s[(32 + lane) * 17 + w + 8];
                const float4* kr2 = ks4 + (32 + lane) * 8;
                const float4* qrA = qek4 + ((w * 2 + 0) * 16 + etA1) * 8;
                const float4* qrB = qek4 + ((w * 2 + 1) * 16 + etB1) * 8;
                int qxA = etA1 & 7, qxB = etB1 & 7;
                float4 aA = {0,0,0,0}, aB = {0,0,0,0};
                #pragma unroll
                for (int c = 0; c < 8; c++) {
                    float4 k4 = kr2[c ^ kx];
                    float4 qa = qrA[c ^ qxA];
                    float4 qc = qrB[c ^ qxB];
                    aA.x += qa.x * k4.x; aA.y += qa.y * k4.y;
                    aA.z += qa.z * k4.z; aA.w += qa.w * k4.w;
                    aB.x += qc.x * k4.x; aB.y += qc.y * k4.y;
                    aB.z += qc.z * k4.z; aB.w += qc.w * k4.w;
                }
                float dA = (aA.x + aA.y) + (aA.z + aA.w);
                float dB = (aB.x + aB.y) + (aB.z + aB.w);
                float bA = bias_s[eb_s[w * 65 + 32 + lane]];
                float bB = bias_s[eb_s[(w + 8) * 65 + 32 + lane]];
                sA1 = (jg <= iA) ? dA * inv_scale + bA : -INFINITY;
                sB1 = (jg <= iB) ? dB * inv_scale + bB : -INFINITY;
            }

            // online softmax, rows A and B
            float tA = fmaxf(sA0, sA1), tB = fmaxf(sB0, sB1);
            #pragma unroll
            for (int o = 16; o; o >>= 1) {
                tA = fmaxf(tA, __shfl_xor_sync(0xffffffffu, tA, o));
                tB = fmaxf(tB, __shfl_xor_sync(0xffffffffu, tB, o));
            }
            float mnA = fmaxf(mA, tA), mnB = fmaxf(mB, tB);
            float pA0 = __expf(sA0 - mnA), pB0 = __expf(sB0 - mnB);
            if (h1) { pA1 = __expf(sA1 - mnA); pB1 = __expf(sB1 - mnB); }
            float psA = pA0 + pA1, psB = pB0 + pB1;
            #pragma unroll
            for (int o = 16; o; o >>= 1) {
                psA += __shfl_xor_sync(0xffffffffu, psA, o);
                psB += __shfl_xor_sync(0xffffffffu, psB, o);
            }
            float cA = __expf(mA - mnA), cB = __expf(mB - mnB);
            lA = lA * cA + psA; lB = lB * cB + psB;
            mA = mnA; mB = mnB;
            #pragma unroll
            for (int u = 0; u < 4; u++) { accA[u] *= cA; accB[u] *= cB; }

            float4* pw = pe_s + w * 64;
            pw[lane] = make_float4(pA0, __int_as_float(etA0 * 132),
                                   pB0, __int_as_float(etB0 * 132));
            if (h1)
                pw[32 + lane] = make_float4(pA1, __int_as_float(etA1 * 132),
                                            pB1, __int_as_float(etB1 * 132));
            __syncwarp();

            // phase 2: lane = e
            int jlim = iB - j0 + 1; if (jlim > 64) jlim = 64;
            int jlim8 = (jlim + 7) & ~7;
            const float* vrow = v_s + lane;
            const char* evb = (const char*)evt_s + lane * 4;
            for (int j8 = 0; j8 < jlim8; j8 += 8) {
                #pragma unroll
                for (int u = 0; u < 8; u++) {
                    float4 pe = pw[j8 + u];
                    float vv = vrow[(j8 + u) * 33];
                    float evA = *(const float*)(evb + __float_as_int(pe.y));
                    float evB = *(const float*)(evb + __float_as_int(pe.w));
                    accA[u & 3] += (pe.x * vv) * evA;
                    accB[u & 3] += (pe.z * vv) * evB;
                }
            }
        }
        __syncthreads();
    }
    float oA = ((accA[0] + accA[1]) + (accA[2] + accA[3])) / lA;
    float oB = ((accB[0] + accB[1]) + (accB[2] + accB[3])) / lB;
    g_y[(size_t)(b * Tt + iA) * Cc + h * Ee + lane] = oA;
    g_y[(size_t)(b * Tt + iB) * Cc + h * Ee + lane] = oB;
}

// ---------------- launch ----------------
extern "C" void kernel_launch(void* const* d_in, const int* in_sizes, int n_in,
                              void* d_out, int out_size) {
    const float* x      = (const float*)d_in[0];
    const int*   bm     = (const int*)d_in[1];
    const float* w_attn = (const float*)d_in[2];
    const float* w_proj = (const float*)d_in[3];
    const float* w_ek   = (const float*)d_in[4];
    const float* w_ev   = (const float*)d_in[5];
    const float* eet    = (const float*)d_in[6];
    const float* abt    = (const float*)d_in[7];
    float* out = (float*)d_out;

    float* gy; cudaGetSymbolAddress((void**)&gy, g_y);

    cudaFuncSetAttribute(attn_kernel, cudaFuncAttributeMaxDynamicSharedMemorySize, SMEM_ATTN);

    // qkv GEMM (bx 0..11) + edge-table blocks (bx 12..13), one launch
    gemm_qkv<<<dim3(14, BT / 32), 256>>>(x, w_attn, eet, w_ek, w_ev);
    // fused attention -> g_y (b,t,c)
    attn_kernel<<<dim3(Tt / 16, Hh, Bb), 256, SMEM_ATTN>>>(bm, abt);
    // out = y @ w_proj
    gemm_out<<<dim3(Cc / 32, BT / 32), 256>>>(gy, w_proj, out);
}

// round 8
// speedup vs baseline: 1.1925x; 1.0585x over previous
#include <cuda_runtime.h>
#include <math.h>
#include <stdint.h>

#define Bb 2
#define Tt 512
#define Cc 256
#define Hh 8
#define Ee 32
#define NET 16
#define BT (Bb*Tt)      // 1024
#define C3 (3*Cc)       // 768
#define HNE (Hh*NET*Ee)

// ------- scratch (device globals: no allocation allowed) -------
__device__ float g_q[Bb*Hh*Tt*Ee];    // (b,h,t,e)
__device__ float g_k[Bb*Hh*Tt*Ee];
__device__ float g_v[Bb*Hh*Tt*Ee];
__device__ float g_ekt[2*HNE];        // 2 k-split partials
__device__ float g_evt[2*HNE];
__device__ float g_y[BT*Cc];          // (b,t,c) pre-proj

// ---------------- cp.async helpers ----------------
__device__ __forceinline__ uint32_t smem_u32(const void* p) {
    uint32_t a;
    asm("{ .reg .u64 t; cvta.to.shared.u64 t, %1; cvt.u32.u64 %0, t; }"
        : "=r"(a) : "l"(p));
    return a;
}
__device__ __forceinline__ void cpa16(uint32_t dst, const void* src) {
    asm volatile("cp.async.ca.shared.global [%0], [%1], 16;" :: "r"(dst), "l"(src));
}
__device__ __forceinline__ void cpa4(uint32_t dst, const void* src) {
    asm volatile("cp.async.ca.shared.global [%0], [%1], 4;" :: "r"(dst), "l"(src));
}

// =====================================================================
// qkv GEMM: 32x64 tile, 128 threads, 4x4 micro, TK=16, double-buffered.
// grid (13, 32): bx 0..11 GEMM, bx==12 -> 32 edge-table blocks.
// =====================================================================
__global__ void __launch_bounds__(128) gemm_qkv(const float* __restrict__ A,
                                                const float* __restrict__ Bm,
                                                const float* __restrict__ eet,
                                                const float* __restrict__ wek,
                                                const float* __restrict__ wev) {
    const int tid = threadIdx.x;

    if (blockIdx.x == 12) {
        // ---- edge-table partial: type t, k-half s, 2 cols/thread ----
        const int t = blockIdx.y >> 1, s = blockIdx.y & 1;
        __shared__ float ee[128];
        ee[tid] = eet[t * Cc + s * 128 + tid];
        __syncthreads();
        const int c0a = tid, c0b = tid + 128;
        const float* wkBase = wek + (size_t)(s * 128) * Cc;
        const float* wvBase = wev + (size_t)(s * 128) * Cc;
        float ska = 0.f, skb = 0.f, sva = 0.f, svb = 0.f;
        #pragma unroll 1
        for (int cb = 0; cb < 128; cb += 8) {
            float wka[8], wkb[8], wva[8], wvb[8];
            #pragma unroll
            for (int u = 0; u < 8; u++) {
                const float* wr = wkBase + (cb + u) * Cc;
                const float* vr = wvBase + (cb + u) * Cc;
                wka[u] = wr[c0a]; wkb[u] = wr[c0b];
                wva[u] = vr[c0a]; wvb[u] = vr[c0b];
            }
            #pragma unroll
            for (int u = 0; u < 8; u++) {
                float a = ee[cb + u];
                ska += a * wka[u]; skb += a * wkb[u];
                sva += a * wva[u]; svb += a * wvb[u];
            }
        }
        int ha = c0a >> 5, ea = c0a & 31;
        int hb = c0b >> 5, eb2 = c0b & 31;
        g_ekt[s * HNE + (ha * NET + t) * Ee + ea] = ska;
        g_ekt[s * HNE + (hb * NET + t) * Ee + eb2] = skb;
        g_evt[s * HNE + (ha * NET + t) * Ee + ea] = sva;
        g_evt[s * HNE + (hb * NET + t) * Ee + eb2] = svb;
        return;
    }

    __shared__ float As[2][16][36];   // k-major
    __shared__ float Bs[2][16][68];
    const int row0 = blockIdx.y * 32;
    const int col0 = blockIdx.x * 64;
    const int ar = tid >> 2, ac = (tid & 3) * 4;
    const int br = tid >> 4, bc = (tid & 15) * 4;
    const int tr = tid >> 4, tc = tid & 15;

    float4 arg, brg0, brg1;
    arg  = *(const float4*)&A[(row0 + ar) * Cc + ac];
    brg0 = *(const float4*)&Bm[br * C3 + col0 + bc];
    brg1 = *(const float4*)&Bm[(br + 8) * C3 + col0 + bc];
    As[0][ac+0][ar] = arg.x; As[0][ac+1][ar] = arg.y;
    As[0][ac+2][ar] = arg.z; As[0][ac+3][ar] = arg.w;
    *(float4*)&Bs[0][br][bc] = brg0;
    *(float4*)&Bs[0][br + 8][bc] = brg1;
    __syncthreads();

    float acc[4][4] = {};
    #pragma unroll 1
    for (int it = 0; it < 16; it++) {
        const int buf = it & 1;
        if (it < 15) {
            int k0 = (it + 1) * 16;
            arg  = *(const float4*)&A[(row0 + ar) * Cc + k0 + ac];
            brg0 = *(const float4*)&Bm[(k0 + br) * C3 + col0 + bc];
            brg1 = *(const float4*)&Bm[(k0 + br + 8) * C3 + col0 + bc];
        }
        #pragma unroll
        for (int kk = 0; kk < 16; kk++) {
            float4 a4 = *(const float4*)&As[buf][kk][tr * 4];
            float4 b4 = *(const float4*)&Bs[buf][kk][tc * 4];
            acc[0][0] += a4.x * b4.x; acc[0][1] += a4.x * b4.y;
            acc[0][2] += a4.x * b4.z; acc[0][3] += a4.x * b4.w;
            acc[1][0] += a4.y * b4.x; acc[1][1] += a4.y * b4.y;
            acc[1][2] += a4.y * b4.z; acc[1][3] += a4.y * b4.w;
            acc[2][0] += a4.z * b4.x; acc[2][1] += a4.z * b4.y;
            acc[2][2] += a4.z * b4.z; acc[2][3] += a4.z * b4.w;
            acc[3][0] += a4.w * b4.x; acc[3][1] += a4.w * b4.y;
            acc[3][2] += a4.w * b4.z; acc[3][3] += a4.w * b4.w;
        }
        if (it < 15) {
            const int nb = buf ^ 1;
            As[nb][ac+0][ar] = arg.x; As[nb][ac+1][ar] = arg.y;
            As[nb][ac+2][ar] = arg.z; As[nb][ac+3][ar] = arg.w;
            *(float4*)&Bs[nb][br][bc] = brg0;
            *(float4*)&Bs[nb][br + 8][bc] = brg1;
            __syncthreads();
        }
    }
    // fused reshape epilogue
    int colbase = col0 + tc * 4;
    int which = colbase >> 8;
    float* dstArr = (which == 0) ? g_q : (which == 1) ? g_k : g_v;
    int h = (colbase & 255) >> 5;
    int e = colbase & 31;
    #pragma unroll
    for (int u = 0; u < 4; u++) {
        int row = row0 + tr * 4 + u;
        int b = row >> 9, t = row & 511;
        *(float4*)&dstArr[(((b * Hh + h) * Tt) + t) * Ee + e] =
            make_float4(acc[u][0], acc[u][1], acc[u][2], acc[u][3]);
    }
}

// ==================== out = g_y @ w_proj: same structure, N=256 ====================
__global__ void __launch_bounds__(128) gemm_out(const float* __restrict__ A,
                                                const float* __restrict__ Bm,
                                                float* __restrict__ Cm) {
    __shared__ float As[2][16][36];
    __shared__ float Bs[2][16][68];
    const int tid = threadIdx.x;
    const int row0 = blockIdx.y * 32;
    const int col0 = blockIdx.x * 64;
    const int ar = tid >> 2, ac = (tid & 3) * 4;
    const int br = tid >> 4, bc = (tid & 15) * 4;
    const int tr = tid >> 4, tc = tid & 15;

    float4 arg, brg0, brg1;
    arg  = *(const float4*)&A[(row0 + ar) * Cc + ac];
    brg0 = *(const float4*)&Bm[br * Cc + col0 + bc];
    brg1 = *(const float4*)&Bm[(br + 8) * Cc + col0 + bc];
    As[0][ac+0][ar] = arg.x; As[0][ac+1][ar] = arg.y;
    As[0][ac+2][ar] = arg.z; As[0][ac+3][ar] = arg.w;
    *(float4*)&Bs[0][br][bc] = brg0;
    *(float4*)&Bs[0][br + 8][bc] = brg1;
    __syncthreads();

    float acc[4][4] = {};
    #pragma unroll 1
    for (int it = 0; it < 16; it++) {
        const int buf = it & 1;
        if (it < 15) {
            int k0 = (it + 1) * 16;
            arg  = *(const float4*)&A[(row0 + ar) * Cc + k0 + ac];
            brg0 = *(const float4*)&Bm[(k0 + br) * Cc + col0 + bc];
            brg1 = *(const float4*)&Bm[(k0 + br + 8) * Cc + col0 + bc];
        }
        #pragma unroll
        for (int kk = 0; kk < 16; kk++) {
            float4 a4 = *(const float4*)&As[buf][kk][tr * 4];
            float4 b4 = *(const float4*)&Bs[buf][kk][tc * 4];
            acc[0][0] += a4.x * b4.x; acc[0][1] += a4.x * b4.y;
            acc[0][2] += a4.x * b4.z; acc[0][3] += a4.x * b4.w;
            acc[1][0] += a4.y * b4.x; acc[1][1] += a4.y * b4.y;
            acc[1][2] += a4.y * b4.z; acc[1][3] += a4.y * b4.w;
            acc[2][0] += a4.z * b4.x; acc[2][1] += a4.z * b4.y;
            acc[2][2] += a4.z * b4.z; acc[2][3] += a4.z * b4.w;
            acc[3][0] += a4.w * b4.x; acc[3][1] += a4.w * b4.y;
            acc[3][2] += a4.w * b4.z; acc[3][3] += a4.w * b4.w;
        }
        if (it < 15) {
            const int nb = buf ^ 1;
            As[nb][ac+0][ar] = arg.x; As[nb][ac+1][ar] = arg.y;
            As[nb][ac+2][ar] = arg.z; As[nb][ac+3][ar] = arg.w;
            *(float4*)&Bs[nb][br][bc] = brg0;
            *(float4*)&Bs[nb][br + 8][bc] = brg1;
            __syncthreads();
        }
    }
    #pragma unroll
    for (int u = 0; u < 4; u++)
        *(float4*)&Cm[(row0 + tr * 4 + u) * Cc + col0 + tc * 4] =
            make_float4(acc[u][0], acc[u][1], acc[u][2], acc[u][3]);
}

// ---------------- fused causal attention: cp.async double-buffered tiles ----------------
// smem layout (bytes):
#define KS_OFF(buf)  ((buf) * 8192)            // float4[64*8] each
#define VS_OFF(buf)  (16384 + (buf) * 9216)    // float[64*36] each
#define ET_OFF(buf)  (34816 + (buf) * 4352)    // int[64*17] each
#define EB_OFF(buf)  (43520 + (buf) * 4160)    // int[16*65] each
#define OFF_QEK  51840                         // float4[8*2*16*8] = 32768
#define OFF_EVT  84608                         // float[16*33]     = 2112
#define OFF_PE   86720                         // float4[8*64]     = 8192
#define OFF_BIAS 94912                         // float[16]
#define SMEM_ATTN 94976

__global__ void __launch_bounds__(256) attn_kernel(const int* __restrict__ bm,
                                                   const float* __restrict__ abt) {
    extern __shared__ char sm[];
    float4* qek4  = (float4*)(sm + OFF_QEK);
    float*  qekf  = (float*) (sm + OFF_QEK);
    float*  evt_s = (float*) (sm + OFF_EVT);
    float4* pe_s  = (float4*)(sm + OFF_PE);
    float*  bias_s= (float*) (sm + OFF_BIAS);
    const uint32_t sbase = smem_u32(sm);

    const int b = blockIdx.z, h = blockIdx.y;
    const int tid = threadIdx.x;
    const int w = tid >> 5, lane = tid & 31;
    const int itile = gridDim.x - 1 - blockIdx.x;   // heavy tiles first
    const int i0 = itile * 16;
    const int iA = i0 + w;
    const int iB = i0 + w + 8;
    const int ntiles = ((i0 + 15) >> 6) + 1;

    const float* qb = g_q + (size_t)(b * Hh + h) * Tt * Ee;
    const float4* kb4 = (const float4*)(g_k + (size_t)(b * Hh + h) * Tt * Ee);
    const float4* vb4 = (const float4*)(g_v + (size_t)(b * Hh + h) * Tt * Ee);
    const int* bm_b = bm + (size_t)b * Tt * Tt;

    // ---- issue tile 0 immediately (overlaps preamble) ----
    auto issue_tile = [&](int tile) {
        const int j0p = tile * 64;
        const int buf = tile & 1;
        const uint32_t ks = sbase + KS_OFF(buf), vs = sbase + VS_OFF(buf);
        const uint32_t et = sbase + ET_OFF(buf), eb = sbase + EB_OFF(buf);
        #pragma unroll
        for (int x = tid; x < 512; x += 256) {
            int jj = x >> 3, c4 = x & 7;
            cpa16(ks + (uint32_t)(jj * 8 + (c4 ^ (jj & 7))) * 16,
                  &kb4[(j0p + jj) * 8 + c4]);
            cpa16(vs + (uint32_t)(jj * 36 + c4 * 4) * 4,
                  &vb4[(j0p + jj) * 8 + c4]);
        }
        #pragma unroll
        for (int x = tid; x < 1024; x += 256) {
            int jj = x >> 4, iw = x & 15;
            cpa4(et + (uint32_t)(jj * 17 + iw) * 4,
                 &bm_b[(j0p + jj) * Tt + i0 + iw]);
        }
        #pragma unroll
        for (int x = tid; x < 1024; x += 256) {
            int iw = x >> 6, jj = x & 63;
            cpa4(eb + (uint32_t)(iw * 65 + jj) * 4,
                 &bm_b[(i0 + iw) * Tt + j0p + jj]);
        }
        asm volatile("cp.async.commit_group;" ::: "memory");
    };
    issue_tile(0);

    // ---- preamble: evt/bias/qek ----
    for (int x = tid; x < NET * Ee; x += 256)
        evt_s[(x >> 5) * 33 + (x & 31)] = g_evt[h * NET * Ee + x] + g_evt[HNE + h * NET * Ee + x];
    if (tid < NET) bias_s[tid] = abt[tid * Hh + h];
    {
        float qA = qb[iA * Ee + lane];
        float qB = qb[iB * Ee + lane];
        int swzbase = lane >> 2;
        #pragma unroll
        for (int t = 0; t < NET; t++) {
            int idx = (h * NET + t) * Ee + lane;
            float ek = g_ekt[idx] + g_ekt[HNE + idx];
            int swz = ((swzbase ^ (t & 7)) << 2) | (lane & 3);
            qekf[((w * 2 + 0) * 16 + t) * 32 + swz] = qA * ek;
            qekf[((w * 2 + 1) * 16 + t) * 32 + swz] = qB * ek;
        }
    }

    float mA = -INFINITY, lA = 0.f, mB = -INFINITY, lB = 0.f;
    float accA[4] = {}, accB[4] = {};
    const float inv_scale = 0.1767766952966369f;   // 1/sqrt(32)

    for (int tile = 0; tile < ntiles; tile++) {
        const int j0 = tile * 64;
        const int buf = tile & 1;
        if (tile + 1 < ntiles) {
            issue_tile(tile + 1);
            asm volatile("cp.async.wait_group 1;" ::: "memory");
        } else {
            asm volatile("cp.async.wait_group 0;" ::: "memory");
        }
        __syncthreads();   // tile data + (tile0) preamble visible

        const float4* ks4 = (const float4*)(sm + KS_OFF(buf));
        const float*  v_s = (const float*) (sm + VS_OFF(buf));
        const int*    et_s= (const int*)   (sm + ET_OFF(buf));
        const int*    eb_s= (const int*)   (sm + EB_OFF(buf));

        {
            const float4* krow = ks4 + lane * 8;
            const int kx = lane & 7;
            float sA0, sB0, sA1 = -INFINITY, sB1 = -INFINITY;
            int etA0, etB0, etA1 = 0, etB1 = 0;
            float pA1 = 0.f, pB1 = 0.f;

            {   // half 0: j = j0 + lane
                int jg = j0 + lane;
                etA0 = et_s[lane * 17 + w];
                etB0 = et_s[lane * 17 + w + 8];
                const float4* qrA = qek4 + ((w * 2 + 0) * 16 + etA0) * 8;
                const float4* qrB = qek4 + ((w * 2 + 1) * 16 + etB0) * 8;
                int qxA = etA0 & 7, qxB = etB0 & 7;
                float4 aA = {0,0,0,0}, aB = {0,0,0,0};
                #pragma unroll
                for (int c = 0; c < 8; c++) {
                    float4 k4 = krow[c ^ kx];
                    float4 qa = qrA[c ^ qxA];
                    float4 qc = qrB[c ^ qxB];
                    aA.x += qa.x * k4.x; aA.y += qa.y * k4.y;
                    aA.z += qa.z * k4.z; aA.w += qa.w * k4.w;
                    aB.x += qc.x * k4.x; aB.y += qc.y * k4.y;
                    aB.z += qc.z * k4.z; aB.w += qc.w * k4.w;
                }
                float dA = (aA.x + aA.y) + (aA.z + aA.w);
                float dB = (aB.x + aB.y) + (aB.z + aB.w);
                float bA = bias_s[eb_s[w * 65 + lane]];
                float bB = bias_s[eb_s[(w + 8) * 65 + lane]];
                sA0 = (jg <= iA) ? dA * inv_scale + bA : -INFINITY;
                sB0 = (jg <= iB) ? dB * inv_scale + bB : -INFINITY;
            }
            const bool h1 = (j0 + 32 <= iB);
            if (h1) {   // half 1
                int jg = j0 + 32 + lane;
                etA1 = et_s[(32 + lane) * 17 + w];
                etB1 = et_s[(32 + lane) * 17 + w + 8];
                const float4* kr2 = ks4 + (32 + lane) * 8;
                const float4* qrA = qek4 + ((w * 2 + 0) * 16 + etA1) * 8;
                const float4* qrB = qek4 + ((w * 2 + 1) * 16 + etB1) * 8;
                int qxA = etA1 & 7, qxB = etB1 & 7;
                float4 aA = {0,0,0,0}, aB = {0,0,0,0};
                #pragma unroll
                for (int c = 0; c < 8; c++) {
                    float4 k4 = kr2[c ^ kx];
                    float4 qa = qrA[c ^ qxA];
                    float4 qc = qrB[c ^ qxB];
                    aA.x += qa.x * k4.x; aA.y += qa.y * k4.y;
                    aA.z += qa.z * k4.z; aA.w += qa.w * k4.w;
                    aB.x += qc.x * k4.x; aB.y += qc.y * k4.y;
                    aB.z += qc.z * k4.z; aB.w += qc.w * k4.w;
                }
                float dA = (aA.x + aA.y) + (aA.z + aA.w);
                float dB = (aB.x + aB.y) + (aB.z + aB.w);
                float bA = bias_s[eb_s[w * 65 + 32 + lane]];
                float bB = bias_s[eb_s[(w + 8) * 65 + 32 + lane]];
                sA1 = (jg <= iA) ? dA * inv_scale + bA : -INFINITY;
                sB1 = (jg <= iB) ? dB * inv_scale + bB : -INFINITY;
            }

            // online softmax, rows A and B
            float tA = fmaxf(sA0, sA1), tB = fmaxf(sB0, sB1);
            #pragma unroll
            for (int o = 16; o; o >>= 1) {
                tA = fmaxf(tA, __shfl_xor_sync(0xffffffffu, tA, o));
                tB = fmaxf(tB, __shfl_xor_sync(0xffffffffu, tB, o));
            }
            float mnA = fmaxf(mA, tA), mnB = fmaxf(mB, tB);
            float pA0 = __expf(sA0 - mnA), pB0 = __expf(sB0 - mnB);
            if (h1) { pA1 = __expf(sA1 - mnA); pB1 = __expf(sB1 - mnB); }
            float psA = pA0 + pA1, psB = pB0 + pB1;
            #pragma unroll
            for (int o = 16; o; o >>= 1) {
                psA += __shfl_xor_sync(0xffffffffu, psA, o);
                psB += __shfl_xor_sync(0xffffffffu, psB, o);
            }
            float cA = __expf(mA - mnA), cB = __expf(mB - mnB);
            lA = lA * cA + psA; lB = lB * cB + psB;
            mA = mnA; mB = mnB;
            #pragma unroll
            for (int u = 0; u < 4; u++) { accA[u] *= cA; accB[u] *= cB; }

            float4* pw = pe_s + w * 64;
            pw[lane] = make_float4(pA0, __int_as_float(etA0 * 132),
                                   pB0, __int_as_float(etB0 * 132));
            if (h1)
                pw[32 + lane] = make_float4(pA1, __int_as_float(etA1 * 132),
                                            pB1, __int_as_float(etB1 * 132));
            __syncwarp();

            // phase 2: lane = e
            int jlim = iB - j0 + 1; if (jlim > 64) jlim = 64;
            int jlim8 = (jlim + 7) & ~7;
            const float* vrow = v_s + lane;
            const char* evb = (const char*)evt_s + lane * 4;
            for (int j8 = 0; j8 < jlim8; j8 += 8) {
                #pragma unroll
                for (int u = 0; u < 8; u++) {
                    float4 pe = pw[j8 + u];
                    float vv = vrow[(j8 + u) * 36];
                    float evA = *(const float*)(evb + __float_as_int(pe.y));
                    float evB = *(const float*)(evb + __float_as_int(pe.w));
                    accA[u & 3] += (pe.x * vv) * evA;
                    accB[u & 3] += (pe.z * vv) * evB;
                }
            }
        }
        __syncthreads();   // compute done before next cp.async overwrites
    }
    float oA = ((accA[0] + accA[1]) + (accA[2] + accA[3])) / lA;
    float oB = ((accB[0] + accB[1]) + (accB[2] + accB[3])) / lB;
    g_y[(size_t)(b * Tt + iA) * Cc + h * Ee + lane] = oA;
    g_y[(size_t)(b * Tt + iB) * Cc + h * Ee + lane] = oB;
}

// ---------------- launch ----------------
extern "C" void kernel_launch(void* const* d_in, const int* in_sizes, int n_in,
                              void* d_out, int out_size) {
    const float* x      = (const float*)d_in[0];
    const int*   bm     = (const int*)d_in[1];
    const float* w_attn = (const float*)d_in[2];
    const float* w_proj = (const float*)d_in[3];
    const float* w_ek   = (const float*)d_in[4];
    const float* w_ev   = (const float*)d_in[5];
    const float* eet    = (const float*)d_in[6];
    const float* abt    = (const float*)d_in[7];
    float* out = (float*)d_out;

    float* gy; cudaGetSymbolAddress((void**)&gy, g_y);

    cudaFuncSetAttribute(attn_kernel, cudaFuncAttributeMaxDynamicSharedMemorySize, SMEM_ATTN);

    // qkv GEMM (bx 0..11) + edge-table blocks (bx 12), one launch
    gemm_qkv<<<dim3(13, BT / 32), 128>>>(x, w_attn, eet, w_ek, w_ev);
    // fused attention -> g_y (b,t,c)
    attn_kernel<<<dim3(Tt / 16, Hh, Bb), 256, SMEM_ATTN>>>(bm, abt);
    // out = y @ w_proj
    gemm_out<<<dim3(Cc / 64, BT / 32), 128>>>(gy, w_proj, out);
}